// round 15
// baseline (speedup 1.0000x reference)
#include <cuda_runtime.h>
#include <cuda_fp16.h>
#include <math.h>
#include <stdint.h>

#define N_NODES 50000
#define N_EDGES 800000
#define NFEAT   512
#define NHID    128
#define NLAYERS 16

#define BM 128
#define BK 64
// gemm_f16 (fc0/fc1): per stage A(16KB)+Bh(16KB)+Bl(16KB)
#define TILE_BYTES  16384
#define STAGE_BYTES 49152
// gemm_layer: per stage A(16KB)+E(16KB); 2 stages resident (no pipeline, K=128)
#define STAGE_L 32768

// ---------------- scratch (device globals) ----------------
__device__ __align__(16)  int   g_deg[N_NODES];
__device__ __align__(16)  float g_dinv[N_NODES];
__device__ __align__(16)  int   g_rowptr[N_NODES + 1];
__device__ __align__(16)  int   g_fill[N_NODES];
__device__ __align__(16)  int2  g_edge[N_EDGES];   // (col, w-bits) interleaved
__device__ __align__(16)  int   g_bsum[64];

__device__ __align__(128) __half g_h0h[(size_t)N_NODES * NHID];
__device__ __align__(128) __half g_h16A[(size_t)N_NODES * NHID];
__device__ __align__(128) __half g_h16B[(size_t)N_NODES * NHID];
__device__ __align__(128) __half g_s16[(size_t)N_NODES * NHID];
__device__ __align__(128) __half g_x16[(size_t)N_NODES * NFEAT];
__device__ __align__(128) __half g_wE[NLAYERS * NHID * NHID];   // E^T = theta*(W-I), [l][n][k]
__device__ __align__(128) __half g_f0h[NHID * NFEAT];
__device__ __align__(128) __half g_f0l[NHID * NFEAT];
__device__ __align__(128) __half g_f1h[NHID * NHID];
__device__ __align__(128) __half g_f1l[NHID * NHID];

// ---------------- PTX helpers (baseline sm_80/sm_90 only) ----------------
__device__ __forceinline__ uint32_t smem_u32(const void* p) {
    uint32_t a;
    asm("{ .reg .u64 t; cvta.to.shared.u64 t, %1; cvt.u32.u64 %0, t; }" : "=r"(a) : "l"(p));
    return a;
}
__device__ __forceinline__ void cp16(uint32_t dst, const void* src, bool valid) {
    asm volatile("cp.async.cg.shared.global [%0], [%1], 16, %2;"
                 :: "r"(dst), "l"(src), "r"(valid ? 16 : 0) : "memory");
}
__device__ __forceinline__ void cp_commit() {
    asm volatile("cp.async.commit_group;" ::: "memory");
}
__device__ __forceinline__ void cp_wait1() {
    asm volatile("cp.async.wait_group 1;" ::: "memory");
}
__device__ __forceinline__ void cp_wait0() {
    asm volatile("cp.async.wait_group 0;" ::: "memory");
}
__device__ __forceinline__ void ldsm4(uint32_t* r, uint32_t addr) {
    asm volatile("ldmatrix.sync.aligned.m8n8.x4.shared.b16 {%0,%1,%2,%3}, [%4];"
                 : "=r"(r[0]), "=r"(r[1]), "=r"(r[2]), "=r"(r[3]) : "r"(addr));
}
__device__ __forceinline__ void mma16816h(float* d, const uint32_t* a, const uint32_t* b) {
    asm volatile("mma.sync.aligned.m16n8k16.row.col.f32.f16.f16.f32 "
                 "{%0,%1,%2,%3}, {%4,%5,%6,%7}, {%8,%9}, {%0,%1,%2,%3};"
                 : "+f"(d[0]), "+f"(d[1]), "+f"(d[2]), "+f"(d[3])
                 : "r"(a[0]), "r"(a[1]), "r"(a[2]), "r"(a[3]), "r"(b[0]), "r"(b[1]));
}
__device__ __forceinline__ uint32_t pack_f16(float a, float b) {
    __half ha = __float2half_rn(a), hb = __float2half_rn(b);
    return ((uint32_t)*(unsigned short*)&hb << 16) | *(unsigned short*)&ha;
}
__device__ __forceinline__ void pdl_wait() {
    asm volatile("griddepcontrol.wait;" ::: "memory");
}
__device__ __forceinline__ void pdl_launch_dep() {
    asm volatile("griddepcontrol.launch_dependents;" ::: "memory");
}

// ---------------- preprocessing kernels ----------------
__global__ void k_init_nodes() {
    int i = blockIdx.x * blockDim.x + threadIdx.x;
    if (i < N_NODES) { g_deg[i] = 1; g_fill[i] = 0; }
}
__global__ void k_count(const int* __restrict__ row) {
    int e = blockIdx.x * blockDim.x + threadIdx.x;
    if (e < N_EDGES) atomicAdd(&g_deg[row[e]], 1);
}
__global__ void k_dinv() {
    int i = blockIdx.x * blockDim.x + threadIdx.x;
    if (i < N_NODES) g_dinv[i] = rsqrtf((float)g_deg[i]);
}
__global__ void k_scanA() {
    __shared__ int ws[32];
    int t = threadIdx.x, lane = t & 31, wid = t >> 5;
    int i = blockIdx.x * 1024 + t;
    int v = (i < N_NODES) ? (g_deg[i] - 1) : 0;
    int x = v;
    #pragma unroll
    for (int off = 1; off < 32; off <<= 1) {
        int y = __shfl_up_sync(0xffffffffu, x, off);
        if (lane >= off) x += y;
    }
    if (lane == 31) ws[wid] = x;
    __syncthreads();
    if (wid == 0) {
        int w = ws[lane];
        int xs = w;
        #pragma unroll
        for (int off = 1; off < 32; off <<= 1) {
            int y = __shfl_up_sync(0xffffffffu, xs, off);
            if (lane >= off) xs += y;
        }
        ws[lane] = xs - w;
    }
    __syncthreads();
    int excl = x - v + ws[wid];
    if (i < N_NODES) g_rowptr[i] = excl;
    if (t == 1023) g_bsum[blockIdx.x] = excl + v;
}
__global__ void k_scanB(int nblk) {
    int s = 0;
    for (int b = 0; b < nblk; b++) { int t = g_bsum[b]; g_bsum[b] = s; s += t; }
    g_rowptr[N_NODES] = s;
}
__global__ void k_scanC() {
    int i = blockIdx.x * blockDim.x + threadIdx.x;
    if (i < N_NODES) g_rowptr[i] += g_bsum[i >> 10];
}
__global__ void k_fill_csr(const int* __restrict__ row, const int* __restrict__ col) {
    int e = blockIdx.x * blockDim.x + threadIdx.x;
    if (e >= N_EDGES) return;
    int r = row[e], c = col[e];
    int pos = g_rowptr[r] + atomicAdd(&g_fill[r], 1);
    float w = 0.9f * g_dinv[r] * g_dinv[c];
    g_edge[pos] = make_int2(c, __float_as_int(w));
}
// E^T[l][n][k] = theta_l * (W[l][k][n] - (k==n))
__global__ void k_wt(const float* __restrict__ cw) {
    int idx = blockIdx.x * blockDim.x + threadIdx.x;
    if (idx >= NLAYERS * NHID * NHID) return;
    int l = idx >> 14, n = (idx >> 7) & 127, k = idx & 127;
    float theta = logf(0.5f / (float)(l + 1) + 1.0f);
    float v = theta * (cw[l * 16384 + k * 128 + n] - (k == n ? 1.0f : 0.0f));
    g_wE[idx] = __float2half_rn(v);
}
__global__ void k_f0t(const float* __restrict__ w) {
    int idx = blockIdx.x * blockDim.x + threadIdx.x;
    if (idx >= NHID * NFEAT) return;
    int n = idx >> 9, k = idx & 511;
    float v = w[k * NHID + n];
    __half h = __float2half_rn(v);
    g_f0h[idx] = h;
    g_f0l[idx] = __float2half_rn(v - __half2float(h));
}
__global__ void k_f1t(const float* __restrict__ w) {
    int idx = blockIdx.x * blockDim.x + threadIdx.x;
    if (idx >= NHID * NHID) return;
    int n = idx >> 7, k = idx & 127;
    float v = w[k * NHID + n];
    __half h = __float2half_rn(v);
    g_f1h[idx] = h;
    g_f1l[idx] = __float2half_rn(v - __half2float(h));
}
__global__ void k_x16(const float* __restrict__ x) {
    int i4 = blockIdx.x * blockDim.x + threadIdx.x;
    if (i4 >= (N_NODES * NFEAT) / 4) return;
    float4 v = ((const float4*)x)[i4];
    ((uint2*)g_x16)[i4] = make_uint2(pack_f16(v.x, v.y), pack_f16(v.z, v.w));
}

// ---------------- SpMM: sup = 0.9*(A_norm h) + 0.1*h0 (all fp16 streams) ----------------
// one warp per row; edge (col,w) pairs batched via one int2 load/lane + shfl broadcast.
__global__ __launch_bounds__(128)
void spmm_kernel(const __half* __restrict__ hin, const __half* __restrict__ h0, int pdl) {
    int gw = (blockIdx.x * blockDim.x + threadIdx.x) >> 5;
    if (gw >= N_NODES) { if (pdl) pdl_wait(); return; }
    int lane = threadIdx.x & 31;

    float dr = g_dinv[gw];
    float sw = 0.9f * dr * dr;
    uint2 ap = ((const uint2*)(h0 + (size_t)gw * NHID))[lane];
    int beg = g_rowptr[gw], end = g_rowptr[gw + 1];
    int2 e_l = make_int2(0, 0);
    {
        int myi = beg + lane;
        if (myi < end) e_l = g_edge[myi];
    }

    if (pdl) pdl_wait();

    uint2 sp = ((const uint2*)(hin + (size_t)gw * NHID))[lane];
    float2 s01 = __half22float2(*(const __half2*)&sp.x);
    float2 s23 = __half22float2(*(const __half2*)&sp.y);
    float2 a01 = __half22float2(*(const __half2*)&ap.x);
    float2 a23 = __half22float2(*(const __half2*)&ap.y);

    float4 acc;
    acc.x = fmaf(sw, s01.x, 0.1f * a01.x);
    acc.y = fmaf(sw, s01.y, 0.1f * a01.y);
    acc.z = fmaf(sw, s23.x, 0.1f * a23.x);
    acc.w = fmaf(sw, s23.y, 0.1f * a23.y);

    for (int base = beg; base < end; base += 32) {
        int n = end - base; if (n > 32) n = 32;
        int2 e_n = make_int2(0, 0);
        {
            int ni = base + 32 + lane;
            if (ni < end) e_n = g_edge[ni];
        }
        #pragma unroll 8
        for (int t = 0; t < n; t++) {
            int   c = __shfl_sync(0xffffffffu, e_l.x, t);
            float w = __int_as_float(__shfl_sync(0xffffffffu, e_l.y, t));
            uint2 vp = ((const uint2*)(hin + (size_t)c * NHID))[lane];
            float2 v01 = __half22float2(*(const __half2*)&vp.x);
            float2 v23 = __half22float2(*(const __half2*)&vp.y);
            acc.x = fmaf(w, v01.x, acc.x);
            acc.y = fmaf(w, v01.y, acc.y);
            acc.z = fmaf(w, v23.x, acc.z);
            acc.w = fmaf(w, v23.y, acc.w);
        }
        e_l = e_n;
    }

    pdl_launch_dep();

    ((uint2*)(g_s16 + (size_t)gw * NHID))[lane] =
        make_uint2(pack_f16(acc.x, acc.y), pack_f16(acc.z, acc.w));
}

// ---------------- layer GEMM: hout = relu(S + S @ E^T), single fp16 product ----------
// 3 CTAs/SM target: smem 64KB, regs capped at 85 via launch bounds.
__global__ __launch_bounds__(256, 3)
void gemm_layer(const __half* __restrict__ A, const __half* __restrict__ B,
                __half* __restrict__ hout, int pdl) {
    extern __shared__ char smem[];
    const uint32_t sb = smem_u32(smem);
    const int tid = threadIdx.x;
    const int warp = tid >> 5, lane = tid & 31;
    const int wm = warp & 3, wn = warp >> 2;
    const int row0 = blockIdx.x * BM;

    const int lr = tid >> 1;
    const int lc0 = (tid & 1) * 4;
    const bool avalid = (row0 + lr) < N_NODES;
    const size_t arow = avalid ? (size_t)(row0 + lr) : 0;

    float acc[2][8][4];
    #pragma unroll
    for (int m = 0; m < 2; m++)
        #pragma unroll
        for (int j = 0; j < 8; j++)
            #pragma unroll
            for (int q = 0; q < 4; q++) acc[m][j][q] = 0.0f;

    // E tiles (weights) before pdl_wait
    #pragma unroll
    for (int s = 0; s < 2; s++) {
        const uint32_t rbase = sb + s * STAGE_L + 16384 + lr * 128;
        const __half* pb = B + (size_t)lr * 128 + s * 64;
        #pragma unroll
        for (int i = 0; i < 4; i++) {
            int c = lc0 + i;
            cp16(rbase + (uint32_t)((c ^ (lr & 7)) << 4), pb + c * 8, true);
        }
    }
    if (pdl) pdl_wait();
    // A tiles (dependent on SpMM)
    #pragma unroll
    for (int s = 0; s < 2; s++) {
        const uint32_t rbase = sb + s * STAGE_L + lr * 128;
        const __half* pa = A + arow * 128 + s * 64;
        #pragma unroll
        for (int i = 0; i < 4; i++) {
            int c = lc0 + i;
            cp16(rbase + (uint32_t)((c ^ (lr & 7)) << 4), pa + c * 8, avalid);
        }
    }
    cp_commit();
    cp_wait0();
    __syncthreads();

    #pragma unroll
    for (int s = 0; s < 2; s++) {
        const uint32_t sbase = sb + s * STAGE_L;
        #pragma unroll
        for (int kk = 0; kk < 4; kk++) {
            uint32_t af[2][4];
            #pragma unroll
            for (int m = 0; m < 2; m++) {
                int r = wm * 32 + m * 16 + (lane & 15);
                int cq = kk * 2 + (lane >> 4);
                uint32_t ad = sbase + r * 128 + (uint32_t)((cq ^ (r & 7)) << 4);
                ldsm4(af[m], ad);
            }
            uint32_t bf[8][2];
            #pragma unroll
            for (int jp = 0; jp < 4; jp++) {
                int g = lane >> 3;
                int nr = wn * 64 + jp * 16 + ((g >> 1) << 3) + (lane & 7);
                int cq = kk * 2 + (g & 1);
                uint32_t bd = sbase + 16384 + nr * 128 +
                              (uint32_t)((cq ^ (nr & 7)) << 4);
                uint32_t t[4];
                ldsm4(t, bd);
                bf[jp * 2][0] = t[0]; bf[jp * 2][1] = t[1];
                bf[jp * 2 + 1][0] = t[2]; bf[jp * 2 + 1][1] = t[3];
            }
            #pragma unroll
            for (int m = 0; m < 2; m++)
                #pragma unroll
                for (int j = 0; j < 8; j++)
                    mma16816h(acc[m][j], af[m], bf[j]);
        }
    }

    pdl_launch_dep();

    // epilogue: out = relu(acc + S) ; S read back from smem A tile (stage = wn)
    #pragma unroll
    for (int m = 0; m < 2; m++) {
        #pragma unroll
        for (int j = 0; j < 8; j++) {
            int cc = wn * 64 + j * 8 + (lane & 3) * 2;
            #pragma unroll
            for (int h = 0; h < 2; h++) {
                int rl = wm * 32 + m * 16 + (lane >> 2) + h * 8;
                int r = row0 + rl;
                if (r < N_NODES) {
                    uint32_t saddr = sb + wn * STAGE_L + rl * 128 +
                                     (uint32_t)(((j ^ (rl & 7)) << 4) + (lane & 3) * 4);
                    uint32_t sv;
                    asm volatile("ld.shared.b32 %0, [%1];" : "=r"(sv) : "r"(saddr));
                    float2 sf = __half22float2(*(const __half2*)&sv);
                    float va = fmaxf(acc[m][j][h * 2 + 0] + sf.x, 0.f);
                    float vb = fmaxf(acc[m][j][h * 2 + 1] + sf.y, 0.f);
                    *(uint32_t*)(hout + (size_t)r * 128 + cc) = pack_f16(va, vb);
                }
            }
        }
    }
}

// ---------------- HMMA fp16 GEMM (fc0/fc1): C = A @ (Bh+Bl)^T (+bias)(+relu) ----------
__global__ __launch_bounds__(256)
void gemm_f16(const __half* __restrict__ A,
              const __half* __restrict__ Bh, const __half* __restrict__ Bl,
              const float* __restrict__ bias,
              float* __restrict__ Cf, __half* __restrict__ C16,
              int M, int K, int do_relu, int pdl) {
    extern __shared__ char smem[];
    const uint32_t sb = smem_u32(smem);
    const int tid = threadIdx.x;
    const int warp = tid >> 5, lane = tid & 31;
    const int wm = warp & 3, wn = warp >> 2;
    const int row0 = blockIdx.x * BM;

    const int lr = tid >> 1;
    const int lc0 = (tid & 1) * 4;
    const bool avalid = (row0 + lr) < M;
    const size_t arow = avalid ? (size_t)(row0 + lr) : 0;

    float acc[2][8][4];
    #pragma unroll
    for (int m = 0; m < 2; m++)
        #pragma unroll
        for (int j = 0; j < 8; j++)
            #pragma unroll
            for (int q = 0; q < 4; q++) acc[m][j][q] = 0.0f;

    const int nchunk = K / BK;

    auto load_stage_B = [&](int s, int k0) {
        const uint32_t rbase = sb + s * STAGE_BYTES + lr * 128;
        const __half* pbh = Bh + (size_t)lr * K + k0;
        const __half* pbl = Bl + (size_t)lr * K + k0;
        #pragma unroll
        for (int i = 0; i < 4; i++) {
            int c = lc0 + i;
            uint32_t off = (uint32_t)((c ^ (lr & 7)) << 4);
            cp16(rbase + TILE_BYTES + off,     pbh + c * 8, true);
            cp16(rbase + 2 * TILE_BYTES + off, pbl + c * 8, true);
        }
    };
    auto load_stage_A = [&](int s, int k0) {
        const uint32_t rbase = sb + s * STAGE_BYTES + lr * 128;
        const __half* pa = A + arow * K + k0;
        #pragma unroll
        for (int i = 0; i < 4; i++) {
            int c = lc0 + i;
            uint32_t off = (uint32_t)((c ^ (lr & 7)) << 4);
            cp16(rbase + off, pa + c * 8, avalid);
        }
    };

    load_stage_B(0, 0);
    if (pdl) pdl_wait();
    load_stage_A(0, 0);
    cp_commit();

    for (int kc = 0; kc < nchunk; kc++) {
        if (kc + 1 < nchunk) {
            load_stage_B((kc + 1) & 1, (kc + 1) * BK);
            load_stage_A((kc + 1) & 1, (kc + 1) * BK);
        }
        cp_commit();
        cp_wait1();
        __syncthreads();
        const uint32_t sbase = sb + (kc & 1) * STAGE_BYTES;
        #pragma unroll
        for (int kk = 0; kk < 4; kk++) {
            uint32_t af[2][4];
            #pragma unroll
            for (int m = 0; m < 2; m++) {
                int r = wm * 32 + m * 16 + (lane & 15);
                int cq = kk * 2 + (lane >> 4);
                uint32_t ad = sbase + r * 128 + (uint32_t)((cq ^ (r & 7)) << 4);
                ldsm4(af[m], ad);
            }
            uint32_t bhf[8][2], blf[8][2];
            #pragma unroll
            for (int jp = 0; jp < 4; jp++) {
                int g = lane >> 3;
                int nr = wn * 64 + jp * 16 + ((g >> 1) << 3) + (lane & 7);
                int cq = kk * 2 + (g & 1);
                uint32_t bd = sbase + TILE_BYTES + nr * 128 +
                              (uint32_t)((cq ^ (nr & 7)) << 4);
                uint32_t t[4];
                ldsm4(t, bd);
                bhf[jp * 2][0] = t[0]; bhf[jp * 2][1] = t[1];
                bhf[jp * 2 + 1][0] = t[2]; bhf[jp * 2 + 1][1] = t[3];
                ldsm4(t, bd + TILE_BYTES);
                blf[jp * 2][0] = t[0]; blf[jp * 2][1] = t[1];
                blf[jp * 2 + 1][0] = t[2]; blf[jp * 2 + 1][1] = t[3];
            }
            #pragma unroll
            for (int m = 0; m < 2; m++)
                #pragma unroll
                for (int j = 0; j < 8; j++) {
                    mma16816h(acc[m][j], af[m], bhf[j]);
                    mma16816h(acc[m][j], af[m], blf[j]);
                }
        }
        __syncthreads();
    }

    pdl_launch_dep();

    #pragma unroll
    for (int m = 0; m < 2; m++) {
        int rbase_ = row0 + wm * 32 + m * 16 + (lane >> 2);
        #pragma unroll
        for (int j = 0; j < 8; j++) {
            int cc = wn * 64 + j * 8 + (lane & 3) * 2;
            float b0v = bias ? bias[cc] : 0.0f;
            float b1v = bias ? bias[cc + 1] : 0.0f;
            float v0 = acc[m][j][0] + b0v, v1 = acc[m][j][1] + b1v;
            float v2 = acc[m][j][2] + b0v, v3 = acc[m][j][3] + b1v;
            if (do_relu) {
                v0 = fmaxf(v0, 0.f); v1 = fmaxf(v1, 0.f);
                v2 = fmaxf(v2, 0.f); v3 = fmaxf(v3, 0.f);
            }
            #pragma unroll
            for (int half_ = 0; half_ < 2; half_++) {
                int r = rbase_ + half_ * 8;
                float va = half_ ? v2 : v0, vb = half_ ? v3 : v1;
                if (r < M) {
                    if (Cf)  *(float2*)(Cf + (size_t)r * 128 + cc) = make_float2(va, vb);
                    if (C16) *(uint32_t*)(C16 + (size_t)r * 128 + cc) = pack_f16(va, vb);
                }
            }
        }
    }
}

// ---------------- launch ----------------
extern "C" void kernel_launch(void* const* d_in, const int* in_sizes, int n_in,
                              void* d_out, int out_size) {
    const float* x      = (const float*)d_in[0];
    const int*   eidx   = (const int*)d_in[1];
    const float* conv_w = (const float*)d_in[2];
    const float* fc0_w  = (const float*)d_in[3];
    const float* fc0_b  = (const float*)d_in[4];
    const float* fc1_w  = (const float*)d_in[5];
    const float* fc1_b  = (const float*)d_in[6];
    float* out = (float*)d_out;
    const int* row = eidx;
    const int* col = eidx + N_EDGES;

    __half *h0h, *h16A, *h16B, *s16, *x16, *wE, *f0h, *f0l, *f1h, *f1l;
    cudaGetSymbolAddress((void**)&h0h,  g_h0h);
    cudaGetSymbolAddress((void**)&h16A, g_h16A);
    cudaGetSymbolAddress((void**)&h16B, g_h16B);
    cudaGetSymbolAddress((void**)&s16,  g_s16);
    cudaGetSymbolAddress((void**)&x16,  g_x16);
    cudaGetSymbolAddress((void**)&wE,   g_wE);
    cudaGetSymbolAddress((void**)&f0h,  g_f0h);
    cudaGetSymbolAddress((void**)&f0l,  g_f0l);
    cudaGetSymbolAddress((void**)&f1h,  g_f1h);
    cudaGetSymbolAddress((void**)&f1l,  g_f1l);

    const int SMEM_BYTES = 2 * STAGE_BYTES;  // 96 KB (fc path)
    const int SMEM_L     = 2 * STAGE_L;      // 64 KB (layer path)
    static cudaStream_t sB = nullptr;
    static cudaEvent_t evFork = nullptr, evJoin = nullptr;
    static int init_done = 0;
    if (!init_done) {
        cudaFuncSetAttribute(gemm_f16, cudaFuncAttributeMaxDynamicSharedMemorySize, SMEM_BYTES);
        cudaFuncSetAttribute(gemm_layer, cudaFuncAttributeMaxDynamicSharedMemorySize, SMEM_L);
        cudaStreamCreateWithFlags(&sB, cudaStreamNonBlocking);
        cudaEventCreateWithFlags(&evFork, cudaEventDisableTiming);
        cudaEventCreateWithFlags(&evJoin, cudaEventDisableTiming);
        init_done = 1;
    }

    const int NB_N = (N_NODES + 255) / 256;
    const int NB_E = (N_EDGES + 255) / 256;
    const int NB_G = (N_NODES + BM - 1) / BM;       // 391
    const int NB_S = (N_NODES + 1023) / 1024;       // 49
    const int NB_SP = (N_NODES * 32 + 127) / 128;   // 12500

    cudaLaunchAttribute pa[1];
    pa[0].id = cudaLaunchAttributeProgrammaticStreamSerialization;
    pa[0].val.programmaticStreamSerializationAllowed = 1;

    cudaLaunchConfig_t cfgS = {};
    cfgS.gridDim = dim3(NB_SP); cfgS.blockDim = dim3(128);
    cfgS.dynamicSmemBytes = 0; cfgS.stream = 0;
    cfgS.attrs = pa; cfgS.numAttrs = 1;

    cudaLaunchConfig_t cfgL = {};
    cfgL.gridDim = dim3(NB_G); cfgL.blockDim = dim3(256);
    cfgL.dynamicSmemBytes = SMEM_L; cfgL.stream = 0;
    cfgL.attrs = pa; cfgL.numAttrs = 1;

    cudaLaunchConfig_t cfgG = {};
    cfgG.gridDim = dim3(NB_G); cfgG.blockDim = dim3(256);
    cfgG.dynamicSmemBytes = SMEM_BYTES; cfgG.stream = 0;
    cfgG.attrs = pa; cfgG.numAttrs = 1;

    // fork: stream B runs the fc0/weights chain concurrently with CSR build
    cudaEventRecord(evFork, 0);
    cudaStreamWaitEvent(sB, evFork, 0);

    k_x16<<<(N_NODES * NFEAT / 4 + 255) / 256, 256, 0, sB>>>(x);
    k_f0t<<<(NHID * NFEAT) / 256, 256, 0, sB>>>(fc0_w);
    k_f1t<<<(NHID * NHID) / 256, 256, 0, sB>>>(fc1_w);
    k_wt<<<(NLAYERS * NHID * NHID) / 256, 256, 0, sB>>>(conv_w);
    gemm_f16<<<NB_G, 256, SMEM_BYTES, sB>>>(x16, f0h, f0l, fc0_b,
                                            nullptr, h0h, N_NODES, NFEAT, 1, 0);
    cudaEventRecord(evJoin, sB);

    // default stream: CSR build
    k_init_nodes<<<NB_N, 256>>>();
    k_count<<<NB_E, 256>>>(row);
    k_dinv<<<NB_N, 256>>>();
    k_scanA<<<NB_S, 1024>>>();
    k_scanB<<<1, 1>>>(NB_S);
    k_scanC<<<NB_N, 256>>>();
    k_fill_csr<<<NB_E, 256>>>(row, col);

    cudaStreamWaitEvent(0, evJoin, 0);

    const __half* hin = h0h;
    for (int l = 0; l < NLAYERS; l++) {
        if (l == 0) {
            spmm_kernel<<<NB_SP, 128>>>(hin, h0h, 0);
        } else {
            cudaLaunchKernelEx(&cfgS, spmm_kernel, hin, (const __half*)h0h, 1);
        }
        __half* hout = (l & 1) ? h16B : h16A;
        cudaLaunchKernelEx(&cfgL, gemm_layer,
                           (const __half*)s16,
                           (const __half*)(wE + (size_t)l * NHID * NHID),
                           hout, 1);
        hin = hout;
    }

    // out = h @ fc1_w + fc1_b
    cudaLaunchKernelEx(&cfgG, gemm_f16,
                       hin, (const __half*)f1h, (const __half*)f1l,
                       (const float*)fc1_b,
                       out, (__half*)nullptr,
                       (int)N_NODES, (int)NHID, 0, 1);
}

// round 17
// speedup vs baseline: 1.1810x; 1.1810x over previous
#include <cuda_runtime.h>
#include <cuda_fp16.h>
#include <math.h>
#include <stdint.h>

#define N_NODES 50000
#define N_EDGES 800000
#define NFEAT   512
#define NHID    128
#define NLAYERS 16

#define BM 128
#define BK 64
// gemm_f16 (fc0/fc1): per stage A(16KB)+Bh(16KB)+Bl(16KB)
#define TILE_BYTES  16384
#define STAGE_BYTES 49152
// gemm_layer: per stage A(16KB)+E(16KB); 2 stages resident (no pipeline, K=128)
#define STAGE_L 32768

// ---------------- scratch (device globals) ----------------
__device__ __align__(16)  int   g_deg[N_NODES];
__device__ __align__(16)  float g_dinv[N_NODES];
__device__ __align__(16)  int   g_rowptr[N_NODES + 1];
__device__ __align__(16)  int   g_fill[N_NODES];
__device__ __align__(16)  int2  g_edge[N_EDGES];   // (col, w-bits) interleaved
__device__ __align__(16)  int   g_bsum[64];

__device__ __align__(128) __half g_h0h[(size_t)N_NODES * NHID];
__device__ __align__(128) __half g_h16A[(size_t)N_NODES * NHID];
__device__ __align__(128) __half g_h16B[(size_t)N_NODES * NHID];
__device__ __align__(128) __half g_s16[(size_t)N_NODES * NHID];
__device__ __align__(128) __half g_x16[(size_t)N_NODES * NFEAT];
__device__ __align__(128) __half g_wE[NLAYERS * NHID * NHID];   // E^T = theta*(W-I), [l][n][k]
__device__ __align__(128) __half g_f0h[NHID * NFEAT];
__device__ __align__(128) __half g_f0l[NHID * NFEAT];
__device__ __align__(128) __half g_f1h[NHID * NHID];
__device__ __align__(128) __half g_f1l[NHID * NHID];

// ---------------- PTX helpers (baseline sm_80/sm_90 only) ----------------
__device__ __forceinline__ uint32_t smem_u32(const void* p) {
    uint32_t a;
    asm("{ .reg .u64 t; cvta.to.shared.u64 t, %1; cvt.u32.u64 %0, t; }" : "=r"(a) : "l"(p));
    return a;
}
__device__ __forceinline__ void cp16(uint32_t dst, const void* src, bool valid) {
    asm volatile("cp.async.cg.shared.global [%0], [%1], 16, %2;"
                 :: "r"(dst), "l"(src), "r"(valid ? 16 : 0) : "memory");
}
__device__ __forceinline__ void cp_commit() {
    asm volatile("cp.async.commit_group;" ::: "memory");
}
__device__ __forceinline__ void cp_wait1() {
    asm volatile("cp.async.wait_group 1;" ::: "memory");
}
__device__ __forceinline__ void cp_wait0() {
    asm volatile("cp.async.wait_group 0;" ::: "memory");
}
__device__ __forceinline__ void ldsm4(uint32_t* r, uint32_t addr) {
    asm volatile("ldmatrix.sync.aligned.m8n8.x4.shared.b16 {%0,%1,%2,%3}, [%4];"
                 : "=r"(r[0]), "=r"(r[1]), "=r"(r[2]), "=r"(r[3]) : "r"(addr));
}
__device__ __forceinline__ void mma16816h(float* d, const uint32_t* a, const uint32_t* b) {
    asm volatile("mma.sync.aligned.m16n8k16.row.col.f32.f16.f16.f32 "
                 "{%0,%1,%2,%3}, {%4,%5,%6,%7}, {%8,%9}, {%0,%1,%2,%3};"
                 : "+f"(d[0]), "+f"(d[1]), "+f"(d[2]), "+f"(d[3])
                 : "r"(a[0]), "r"(a[1]), "r"(a[2]), "r"(a[3]), "r"(b[0]), "r"(b[1]));
}
__device__ __forceinline__ uint32_t pack_f16(float a, float b) {
    __half ha = __float2half_rn(a), hb = __float2half_rn(b);
    return ((uint32_t)*(unsigned short*)&hb << 16) | *(unsigned short*)&ha;
}
__device__ __forceinline__ void pdl_wait() {
    asm volatile("griddepcontrol.wait;" ::: "memory");
}
__device__ __forceinline__ void pdl_launch_dep() {
    asm volatile("griddepcontrol.launch_dependents;" ::: "memory");
}

// ---------------- preprocessing kernels ----------------
__global__ void k_init_nodes() {
    int i = blockIdx.x * blockDim.x + threadIdx.x;
    if (i < N_NODES) { g_deg[i] = 1; g_fill[i] = 0; }
}
__global__ void k_count(const int* __restrict__ row) {
    int e = blockIdx.x * blockDim.x + threadIdx.x;
    if (e < N_EDGES) atomicAdd(&g_deg[row[e]], 1);
}
__global__ void k_dinv() {
    int i = blockIdx.x * blockDim.x + threadIdx.x;
    if (i < N_NODES) g_dinv[i] = rsqrtf((float)g_deg[i]);
}
__global__ void k_scanA() {
    __shared__ int ws[32];
    int t = threadIdx.x, lane = t & 31, wid = t >> 5;
    int i = blockIdx.x * 1024 + t;
    int v = (i < N_NODES) ? (g_deg[i] - 1) : 0;
    int x = v;
    #pragma unroll
    for (int off = 1; off < 32; off <<= 1) {
        int y = __shfl_up_sync(0xffffffffu, x, off);
        if (lane >= off) x += y;
    }
    if (lane == 31) ws[wid] = x;
    __syncthreads();
    if (wid == 0) {
        int w = ws[lane];
        int xs = w;
        #pragma unroll
        for (int off = 1; off < 32; off <<= 1) {
            int y = __shfl_up_sync(0xffffffffu, xs, off);
            if (lane >= off) xs += y;
        }
        ws[lane] = xs - w;
    }
    __syncthreads();
    int excl = x - v + ws[wid];
    if (i < N_NODES) g_rowptr[i] = excl;
    if (t == 1023) g_bsum[blockIdx.x] = excl + v;
}
__global__ void k_scanB(int nblk) {
    int s = 0;
    for (int b = 0; b < nblk; b++) { int t = g_bsum[b]; g_bsum[b] = s; s += t; }
    g_rowptr[N_NODES] = s;
}
__global__ void k_scanC() {
    int i = blockIdx.x * blockDim.x + threadIdx.x;
    if (i < N_NODES) g_rowptr[i] += g_bsum[i >> 10];
}
__global__ void k_fill_csr(const int* __restrict__ row, const int* __restrict__ col) {
    int e = blockIdx.x * blockDim.x + threadIdx.x;
    if (e >= N_EDGES) return;
    int r = row[e], c = col[e];
    int pos = g_rowptr[r] + atomicAdd(&g_fill[r], 1);
    float w = 0.9f * g_dinv[r] * g_dinv[c];
    g_edge[pos] = make_int2(c, __float_as_int(w));
}
// E^T[l][n][k] = theta_l * (W[l][k][n] - (k==n))
__global__ void k_wt(const float* __restrict__ cw) {
    int idx = blockIdx.x * blockDim.x + threadIdx.x;
    if (idx >= NLAYERS * NHID * NHID) return;
    int l = idx >> 14, n = (idx >> 7) & 127, k = idx & 127;
    float theta = logf(0.5f / (float)(l + 1) + 1.0f);
    float v = theta * (cw[l * 16384 + k * 128 + n] - (k == n ? 1.0f : 0.0f));
    g_wE[idx] = __float2half_rn(v);
}
__global__ void k_f0t(const float* __restrict__ w) {
    int idx = blockIdx.x * blockDim.x + threadIdx.x;
    if (idx >= NHID * NFEAT) return;
    int n = idx >> 9, k = idx & 511;
    float v = w[k * NHID + n];
    __half h = __float2half_rn(v);
    g_f0h[idx] = h;
    g_f0l[idx] = __float2half_rn(v - __half2float(h));
}
__global__ void k_f1t(const float* __restrict__ w) {
    int idx = blockIdx.x * blockDim.x + threadIdx.x;
    if (idx >= NHID * NHID) return;
    int n = idx >> 7, k = idx & 127;
    float v = w[k * NHID + n];
    __half h = __float2half_rn(v);
    g_f1h[idx] = h;
    g_f1l[idx] = __float2half_rn(v - __half2float(h));
}
__global__ void k_x16(const float* __restrict__ x) {
    int i4 = blockIdx.x * blockDim.x + threadIdx.x;
    if (i4 >= (N_NODES * NFEAT) / 4) return;
    float4 v = ((const float4*)x)[i4];
    ((uint2*)g_x16)[i4] = make_uint2(pack_f16(v.x, v.y), pack_f16(v.z, v.w));
}

// ---------------- SpMM: sup = 0.9*(A_norm h) + 0.1*h0 (all fp16 streams) ----------------
// one warp per row; edge (col,w) pairs batched via one int2 load/lane + shfl broadcast.
__global__ __launch_bounds__(128)
void spmm_kernel(const __half* __restrict__ hin, const __half* __restrict__ h0, int pdl) {
    int gw = (blockIdx.x * blockDim.x + threadIdx.x) >> 5;
    if (gw >= N_NODES) { if (pdl) pdl_wait(); return; }
    int lane = threadIdx.x & 31;

    float dr = g_dinv[gw];
    float sw = 0.9f * dr * dr;
    uint2 ap = ((const uint2*)(h0 + (size_t)gw * NHID))[lane];
    int beg = g_rowptr[gw], end = g_rowptr[gw + 1];
    int2 e_l = make_int2(0, 0);
    {
        int myi = beg + lane;
        if (myi < end) e_l = g_edge[myi];
    }

    if (pdl) pdl_wait();

    uint2 sp = ((const uint2*)(hin + (size_t)gw * NHID))[lane];
    float2 s01 = __half22float2(*(const __half2*)&sp.x);
    float2 s23 = __half22float2(*(const __half2*)&sp.y);
    float2 a01 = __half22float2(*(const __half2*)&ap.x);
    float2 a23 = __half22float2(*(const __half2*)&ap.y);

    float4 acc;
    acc.x = fmaf(sw, s01.x, 0.1f * a01.x);
    acc.y = fmaf(sw, s01.y, 0.1f * a01.y);
    acc.z = fmaf(sw, s23.x, 0.1f * a23.x);
    acc.w = fmaf(sw, s23.y, 0.1f * a23.y);

    for (int base = beg; base < end; base += 32) {
        int n = end - base; if (n > 32) n = 32;
        int2 e_n = make_int2(0, 0);
        {
            int ni = base + 32 + lane;
            if (ni < end) e_n = g_edge[ni];
        }
        #pragma unroll 8
        for (int t = 0; t < n; t++) {
            int   c = __shfl_sync(0xffffffffu, e_l.x, t);
            float w = __int_as_float(__shfl_sync(0xffffffffu, e_l.y, t));
            uint2 vp = ((const uint2*)(hin + (size_t)c * NHID))[lane];
            float2 v01 = __half22float2(*(const __half2*)&vp.x);
            float2 v23 = __half22float2(*(const __half2*)&vp.y);
            acc.x = fmaf(w, v01.x, acc.x);
            acc.y = fmaf(w, v01.y, acc.y);
            acc.z = fmaf(w, v23.x, acc.z);
            acc.w = fmaf(w, v23.y, acc.w);
        }
        e_l = e_n;
    }

    pdl_launch_dep();

    ((uint2*)(g_s16 + (size_t)gw * NHID))[lane] =
        make_uint2(pack_f16(acc.x, acc.y), pack_f16(acc.z, acc.w));
}

// ---------------- layer GEMM: hout = relu(S + S @ E^T), single fp16 product ----------
// Natural regs (~110), 2 CTAs/SM — the R12 configuration (679.7us). No reg cap.
__global__ __launch_bounds__(256)
void gemm_layer(const __half* __restrict__ A, const __half* __restrict__ B,
                __half* __restrict__ hout, int pdl) {
    extern __shared__ char smem[];
    const uint32_t sb = smem_u32(smem);
    const int tid = threadIdx.x;
    const int warp = tid >> 5, lane = tid & 31;
    const int wm = warp & 3, wn = warp >> 2;
    const int row0 = blockIdx.x * BM;

    const int lr = tid >> 1;
    const int lc0 = (tid & 1) * 4;
    const bool avalid = (row0 + lr) < N_NODES;
    const size_t arow = avalid ? (size_t)(row0 + lr) : 0;

    float acc[2][8][4];
    #pragma unroll
    for (int m = 0; m < 2; m++)
        #pragma unroll
        for (int j = 0; j < 8; j++)
            #pragma unroll
            for (int q = 0; q < 4; q++) acc[m][j][q] = 0.0f;

    // E tiles (weights) before pdl_wait
    #pragma unroll
    for (int s = 0; s < 2; s++) {
        const uint32_t rbase = sb + s * STAGE_L + 16384 + lr * 128;
        const __half* pb = B + (size_t)lr * 128 + s * 64;
        #pragma unroll
        for (int i = 0; i < 4; i++) {
            int c = lc0 + i;
            cp16(rbase + (uint32_t)((c ^ (lr & 7)) << 4), pb + c * 8, true);
        }
    }
    if (pdl) pdl_wait();
    // A tiles (dependent on SpMM)
    #pragma unroll
    for (int s = 0; s < 2; s++) {
        const uint32_t rbase = sb + s * STAGE_L + lr * 128;
        const __half* pa = A + arow * 128 + s * 64;
        #pragma unroll
        for (int i = 0; i < 4; i++) {
            int c = lc0 + i;
            cp16(rbase + (uint32_t)((c ^ (lr & 7)) << 4), pa + c * 8, avalid);
        }
    }
    cp_commit();
    cp_wait0();
    __syncthreads();

    #pragma unroll
    for (int s = 0; s < 2; s++) {
        const uint32_t sbase = sb + s * STAGE_L;
        #pragma unroll
        for (int kk = 0; kk < 4; kk++) {
            uint32_t af[2][4];
            #pragma unroll
            for (int m = 0; m < 2; m++) {
                int r = wm * 32 + m * 16 + (lane & 15);
                int cq = kk * 2 + (lane >> 4);
                uint32_t ad = sbase + r * 128 + (uint32_t)((cq ^ (r & 7)) << 4);
                ldsm4(af[m], ad);
            }
            uint32_t bf[8][2];
            #pragma unroll
            for (int jp = 0; jp < 4; jp++) {
                int g = lane >> 3;
                int nr = wn * 64 + jp * 16 + ((g >> 1) << 3) + (lane & 7);
                int cq = kk * 2 + (g & 1);
                uint32_t bd = sbase + 16384 + nr * 128 +
                              (uint32_t)((cq ^ (nr & 7)) << 4);
                uint32_t t[4];
                ldsm4(t, bd);
                bf[jp * 2][0] = t[0]; bf[jp * 2][1] = t[1];
                bf[jp * 2 + 1][0] = t[2]; bf[jp * 2 + 1][1] = t[3];
            }
            #pragma unroll
            for (int m = 0; m < 2; m++)
                #pragma unroll
                for (int j = 0; j < 8; j++)
                    mma16816h(acc[m][j], af[m], bf[j]);
        }
    }

    pdl_launch_dep();

    // epilogue: out = relu(acc + S) ; S read back from smem A tile (stage = wn)
    #pragma unroll
    for (int m = 0; m < 2; m++) {
        #pragma unroll
        for (int j = 0; j < 8; j++) {
            int cc = wn * 64 + j * 8 + (lane & 3) * 2;
            #pragma unroll
            for (int h = 0; h < 2; h++) {
                int rl = wm * 32 + m * 16 + (lane >> 2) + h * 8;
                int r = row0 + rl;
                if (r < N_NODES) {
                    uint32_t saddr = sb + wn * STAGE_L + rl * 128 +
                                     (uint32_t)(((j ^ (rl & 7)) << 4) + (lane & 3) * 4);
                    uint32_t sv;
                    asm volatile("ld.shared.b32 %0, [%1];" : "=r"(sv) : "r"(saddr));
                    float2 sf = __half22float2(*(const __half2*)&sv);
                    float va = fmaxf(acc[m][j][h * 2 + 0] + sf.x, 0.f);
                    float vb = fmaxf(acc[m][j][h * 2 + 1] + sf.y, 0.f);
                    *(uint32_t*)(hout + (size_t)r * 128 + cc) = pack_f16(va, vb);
                }
            }
        }
    }
}

// ---------------- HMMA fp16 GEMM (fc0/fc1): C = A @ (Bh+Bl)^T (+bias)(+relu) ----------
__global__ __launch_bounds__(256)
void gemm_f16(const __half* __restrict__ A,
              const __half* __restrict__ Bh, const __half* __restrict__ Bl,
              const float* __restrict__ bias,
              float* __restrict__ Cf, __half* __restrict__ C16,
              int M, int K, int do_relu, int pdl) {
    extern __shared__ char smem[];
    const uint32_t sb = smem_u32(smem);
    const int tid = threadIdx.x;
    const int warp = tid >> 5, lane = tid & 31;
    const int wm = warp & 3, wn = warp >> 2;
    const int row0 = blockIdx.x * BM;

    const int lr = tid >> 1;
    const int lc0 = (tid & 1) * 4;
    const bool avalid = (row0 + lr) < M;
    const size_t arow = avalid ? (size_t)(row0 + lr) : 0;

    float acc[2][8][4];
    #pragma unroll
    for (int m = 0; m < 2; m++)
        #pragma unroll
        for (int j = 0; j < 8; j++)
            #pragma unroll
            for (int q = 0; q < 4; q++) acc[m][j][q] = 0.0f;

    const int nchunk = K / BK;

    auto load_stage_B = [&](int s, int k0) {
        const uint32_t rbase = sb + s * STAGE_BYTES + lr * 128;
        const __half* pbh = Bh + (size_t)lr * K + k0;
        const __half* pbl = Bl + (size_t)lr * K + k0;
        #pragma unroll
        for (int i = 0; i < 4; i++) {
            int c = lc0 + i;
            uint32_t off = (uint32_t)((c ^ (lr & 7)) << 4);
            cp16(rbase + TILE_BYTES + off,     pbh + c * 8, true);
            cp16(rbase + 2 * TILE_BYTES + off, pbl + c * 8, true);
        }
    };
    auto load_stage_A = [&](int s, int k0) {
        const uint32_t rbase = sb + s * STAGE_BYTES + lr * 128;
        const __half* pa = A + arow * K + k0;
        #pragma unroll
        for (int i = 0; i < 4; i++) {
            int c = lc0 + i;
            uint32_t off = (uint32_t)((c ^ (lr & 7)) << 4);
            cp16(rbase + off, pa + c * 8, avalid);
        }
    };

    load_stage_B(0, 0);
    if (pdl) pdl_wait();
    load_stage_A(0, 0);
    cp_commit();

    for (int kc = 0; kc < nchunk; kc++) {
        if (kc + 1 < nchunk) {
            load_stage_B((kc + 1) & 1, (kc + 1) * BK);
            load_stage_A((kc + 1) & 1, (kc + 1) * BK);
        }
        cp_commit();
        cp_wait1();
        __syncthreads();
        const uint32_t sbase = sb + (kc & 1) * STAGE_BYTES;
        #pragma unroll
        for (int kk = 0; kk < 4; kk++) {
            uint32_t af[2][4];
            #pragma unroll
            for (int m = 0; m < 2; m++) {
                int r = wm * 32 + m * 16 + (lane & 15);
                int cq = kk * 2 + (lane >> 4);
                uint32_t ad = sbase + r * 128 + (uint32_t)((cq ^ (r & 7)) << 4);
                ldsm4(af[m], ad);
            }
            uint32_t bhf[8][2], blf[8][2];
            #pragma unroll
            for (int jp = 0; jp < 4; jp++) {
                int g = lane >> 3;
                int nr = wn * 64 + jp * 16 + ((g >> 1) << 3) + (lane & 7);
                int cq = kk * 2 + (g & 1);
                uint32_t bd = sbase + TILE_BYTES + nr * 128 +
                              (uint32_t)((cq ^ (nr & 7)) << 4);
                uint32_t t[4];
                ldsm4(t, bd);
                bhf[jp * 2][0] = t[0]; bhf[jp * 2][1] = t[1];
                bhf[jp * 2 + 1][0] = t[2]; bhf[jp * 2 + 1][1] = t[3];
                ldsm4(t, bd + TILE_BYTES);
                blf[jp * 2][0] = t[0]; blf[jp * 2][1] = t[1];
                blf[jp * 2 + 1][0] = t[2]; blf[jp * 2 + 1][1] = t[3];
            }
            #pragma unroll
            for (int m = 0; m < 2; m++)
                #pragma unroll
                for (int j = 0; j < 8; j++) {
                    mma16816h(acc[m][j], af[m], bhf[j]);
                    mma16816h(acc[m][j], af[m], blf[j]);
                }
        }
        __syncthreads();
    }

    pdl_launch_dep();

    #pragma unroll
    for (int m = 0; m < 2; m++) {
        int rbase_ = row0 + wm * 32 + m * 16 + (lane >> 2);
        #pragma unroll
        for (int j = 0; j < 8; j++) {
            int cc = wn * 64 + j * 8 + (lane & 3) * 2;
            float b0v = bias ? bias[cc] : 0.0f;
            float b1v = bias ? bias[cc + 1] : 0.0f;
            float v0 = acc[m][j][0] + b0v, v1 = acc[m][j][1] + b1v;
            float v2 = acc[m][j][2] + b0v, v3 = acc[m][j][3] + b1v;
            if (do_relu) {
                v0 = fmaxf(v0, 0.f); v1 = fmaxf(v1, 0.f);
                v2 = fmaxf(v2, 0.f); v3 = fmaxf(v3, 0.f);
            }
            #pragma unroll
            for (int half_ = 0; half_ < 2; half_++) {
                int r = rbase_ + half_ * 8;
                float va = half_ ? v2 : v0, vb = half_ ? v3 : v1;
                if (r < M) {
                    if (Cf)  *(float2*)(Cf + (size_t)r * 128 + cc) = make_float2(va, vb);
                    if (C16) *(uint32_t*)(C16 + (size_t)r * 128 + cc) = pack_f16(va, vb);
                }
            }
        }
    }
}

// ---------------- launch ----------------
extern "C" void kernel_launch(void* const* d_in, const int* in_sizes, int n_in,
                              void* d_out, int out_size) {
    const float* x      = (const float*)d_in[0];
    const int*   eidx   = (const int*)d_in[1];
    const float* conv_w = (const float*)d_in[2];
    const float* fc0_w  = (const float*)d_in[3];
    const float* fc0_b  = (const float*)d_in[4];
    const float* fc1_w  = (const float*)d_in[5];
    const float* fc1_b  = (const float*)d_in[6];
    float* out = (float*)d_out;
    const int* row = eidx;
    const int* col = eidx + N_EDGES;

    __half *h0h, *h16A, *h16B, *s16, *x16, *wE, *f0h, *f0l, *f1h, *f1l;
    cudaGetSymbolAddress((void**)&h0h,  g_h0h);
    cudaGetSymbolAddress((void**)&h16A, g_h16A);
    cudaGetSymbolAddress((void**)&h16B, g_h16B);
    cudaGetSymbolAddress((void**)&s16,  g_s16);
    cudaGetSymbolAddress((void**)&x16,  g_x16);
    cudaGetSymbolAddress((void**)&wE,   g_wE);
    cudaGetSymbolAddress((void**)&f0h,  g_f0h);
    cudaGetSymbolAddress((void**)&f0l,  g_f0l);
    cudaGetSymbolAddress((void**)&f1h,  g_f1h);
    cudaGetSymbolAddress((void**)&f1l,  g_f1l);

    const int SMEM_BYTES = 2 * STAGE_BYTES;  // 96 KB (fc path)
    const int SMEM_L     = 2 * STAGE_L;      // 64 KB (layer path)
    static cudaStream_t sB = nullptr;
    static cudaEvent_t evFork = nullptr, evJoin = nullptr;
    static int init_done = 0;
    if (!init_done) {
        cudaFuncSetAttribute(gemm_f16, cudaFuncAttributeMaxDynamicSharedMemorySize, SMEM_BYTES);
        cudaFuncSetAttribute(gemm_layer, cudaFuncAttributeMaxDynamicSharedMemorySize, SMEM_L);
        cudaStreamCreateWithFlags(&sB, cudaStreamNonBlocking);
        cudaEventCreateWithFlags(&evFork, cudaEventDisableTiming);
        cudaEventCreateWithFlags(&evJoin, cudaEventDisableTiming);
        init_done = 1;
    }

    const int NB_N = (N_NODES + 255) / 256;
    const int NB_E = (N_EDGES + 255) / 256;
    const int NB_G = (N_NODES + BM - 1) / BM;       // 391
    const int NB_S = (N_NODES + 1023) / 1024;       // 49
    const int NB_SP = (N_NODES * 32 + 127) / 128;   // 12500

    cudaLaunchAttribute pa[1];
    pa[0].id = cudaLaunchAttributeProgrammaticStreamSerialization;
    pa[0].val.programmaticStreamSerializationAllowed = 1;

    cudaLaunchConfig_t cfgS = {};
    cfgS.gridDim = dim3(NB_SP); cfgS.blockDim = dim3(128);
    cfgS.dynamicSmemBytes = 0; cfgS.stream = 0;
    cfgS.attrs = pa; cfgS.numAttrs = 1;

    cudaLaunchConfig_t cfgL = {};
    cfgL.gridDim = dim3(NB_G); cfgL.blockDim = dim3(256);
    cfgL.dynamicSmemBytes = SMEM_L; cfgL.stream = 0;
    cfgL.attrs = pa; cfgL.numAttrs = 1;

    cudaLaunchConfig_t cfgG = {};
    cfgG.gridDim = dim3(NB_G); cfgG.blockDim = dim3(256);
    cfgG.dynamicSmemBytes = SMEM_BYTES; cfgG.stream = 0;
    cfgG.attrs = pa; cfgG.numAttrs = 1;

    // fork: stream B runs the fc0/weights chain concurrently with CSR build
    cudaEventRecord(evFork, 0);
    cudaStreamWaitEvent(sB, evFork, 0);

    k_x16<<<(N_NODES * NFEAT / 4 + 255) / 256, 256, 0, sB>>>(x);
    k_f0t<<<(NHID * NFEAT) / 256, 256, 0, sB>>>(fc0_w);
    k_f1t<<<(NHID * NHID) / 256, 256, 0, sB>>>(fc1_w);
    k_wt<<<(NLAYERS * NHID * NHID) / 256, 256, 0, sB>>>(conv_w);
    gemm_f16<<<NB_G, 256, SMEM_BYTES, sB>>>(x16, f0h, f0l, fc0_b,
                                            nullptr, h0h, N_NODES, NFEAT, 1, 0);
    cudaEventRecord(evJoin, sB);

    // default stream: CSR build
    k_init_nodes<<<NB_N, 256>>>();
    k_count<<<NB_E, 256>>>(row);
    k_dinv<<<NB_N, 256>>>();
    k_scanA<<<NB_S, 1024>>>();
    k_scanB<<<1, 1>>>(NB_S);
    k_scanC<<<NB_N, 256>>>();
    k_fill_csr<<<NB_E, 256>>>(row, col);

    cudaStreamWaitEvent(0, evJoin, 0);

    const __half* hin = h0h;
    for (int l = 0; l < NLAYERS; l++) {
        if (l == 0) {
            spmm_kernel<<<NB_SP, 128>>>(hin, h0h, 0);
        } else {
            cudaLaunchKernelEx(&cfgS, spmm_kernel, hin, (const __half*)h0h, 1);
        }
        __half* hout = (l & 1) ? h16B : h16A;
        cudaLaunchKernelEx(&cfgL, gemm_layer,
                           (const __half*)s16,
                           (const __half*)(wE + (size_t)l * NHID * NHID),
                           hout, 1);
        hin = hout;
    }

    // out = h @ fc1_w + fc1_b
    cudaLaunchKernelEx(&cfgG, gemm_f16,
                       hin, (const __half*)f1h, (const __half*)f1l,
                       (const float*)fc1_b,
                       out, (__half*)nullptr,
                       (int)N_NODES, (int)NHID, 0, 1);
}